// round 1
// baseline (speedup 1.0000x reference)
#include <cuda_runtime.h>

#define H_  16
#define HS_ 64
#define C_  1024
#define T_  2048
#define B_  2
#define BT_ (B_ * T_)   // 4096

// Scratch (no device allocation allowed)
__device__ float g_q[B_ * H_ * T_ * HS_];
__device__ float g_k[B_ * H_ * T_ * HS_];
__device__ float g_v[B_ * H_ * T_ * HS_];
__device__ float g_att[BT_ * C_];

// ---------------------------------------------------------------------------
// Fused QKV projection: out[n] for n in [0,3072): (qkv, h, d)
// q/k/v[b,h,t,d] = sum_c x[b,t,c] * W{q,k,v}[h,c,d]
// Classic 128x128x8 fp32 tile, 8x8 register micro-tiles.
// ---------------------------------------------------------------------------
__global__ __launch_bounds__(256) void qkv_gemm(
    const float* __restrict__ x,
    const float* __restrict__ Wq,
    const float* __restrict__ Wk,
    const float* __restrict__ Wv)
{
    __shared__ float As[8][128];   // A transposed: As[k][m]
    __shared__ float Bs[8][128];   // Bs[k][n]

    const int tid = threadIdx.x;
    const int m0 = blockIdx.y * 128;
    const int n0 = blockIdx.x * 128;
    const int tx = tid & 15;
    const int ty = tid >> 4;

    // A tile load mapping: one float4 per thread per k-tile
    const int arow = tid >> 1;             // 0..127
    const int akk  = (tid & 1) * 4;        // 0 or 4
    const float* Aptr = x + (size_t)(m0 + arow) * C_ + akk;

    // B tile load mapping: one float4 per thread per k-tile
    const int bln = (tid & 31) * 4;        // col-in-tile 0..124
    const int bkk = tid >> 5;              // 0..7
    const int gn  = n0 + bln;
    const int qkv = gn >> 10;
    const int hh  = (gn >> 6) & (H_ - 1);
    const int dd  = gn & (HS_ - 1);
    const float* Wsel = (qkv == 0) ? Wq : (qkv == 1) ? Wk : Wv;
    const float* bcol = Wsel + (size_t)hh * (C_ * HS_) + dd;   // + k*HS_

    float acc[8][8];
#pragma unroll
    for (int i = 0; i < 8; i++)
#pragma unroll
        for (int j = 0; j < 8; j++) acc[i][j] = 0.f;

    for (int k0 = 0; k0 < C_; k0 += 8) {
        float4 av = *(const float4*)(Aptr + k0);
        As[akk + 0][arow] = av.x;
        As[akk + 1][arow] = av.y;
        As[akk + 2][arow] = av.z;
        As[akk + 3][arow] = av.w;
        *(float4*)&Bs[bkk][bln] =
            *(const float4*)(bcol + (size_t)(k0 + bkk) * HS_);
        __syncthreads();
#pragma unroll
        for (int kk = 0; kk < 8; kk++) {
            float a[8], b[8];
            *(float4*)&a[0] = *(const float4*)&As[kk][ty * 8];
            *(float4*)&a[4] = *(const float4*)&As[kk][ty * 8 + 4];
            *(float4*)&b[0] = *(const float4*)&Bs[kk][tx * 8];
            *(float4*)&b[4] = *(const float4*)&Bs[kk][tx * 8 + 4];
#pragma unroll
            for (int i = 0; i < 8; i++)
#pragma unroll
                for (int j = 0; j < 8; j++)
                    acc[i][j] += a[i] * b[j];
        }
        __syncthreads();
    }

    // Scatter to g_q/g_k/g_v with [B,H,T,HS] layout
#pragma unroll
    for (int i = 0; i < 8; i++) {
        int m = m0 + ty * 8 + i;
        int b = m >> 11;            // /T_
        int t = m & (T_ - 1);
#pragma unroll
        for (int j = 0; j < 8; j++) {
            int n  = n0 + tx * 8 + j;
            int qk = n >> 10;
            int h2 = (n >> 6) & (H_ - 1);
            int d2 = n & (HS_ - 1);
            float* dst = (qk == 0) ? g_q : (qk == 1) ? g_k : g_v;
            dst[(((size_t)b * H_ + h2) * T_ + t) * HS_ + d2] = acc[i][j];
        }
    }
}

// ---------------------------------------------------------------------------
// Flash attention, fp32, causal. One block = 64 query rows of one (b,h);
// 64 threads, one query row per thread (Q row + O accumulator in registers).
// K/V tiles (64x64) staged in SMEM; online softmax over 16-key chunks.
// Writes g_att[b, t, h*HS + d] (head-concat layout for the output GEMM).
// ---------------------------------------------------------------------------
__global__ __launch_bounds__(64) void flash_attn()
{
    const int qt  = blockIdx.x;         // query tile 0..31
    const int bh  = blockIdx.y;         // 0..31
    const int tid = threadIdx.x;        // row within tile
    const int q0   = qt * 64;
    const int qrow = q0 + tid;

    const float* qb = g_q + (size_t)bh * T_ * HS_;
    const float* kb = g_k + (size_t)bh * T_ * HS_;
    const float* vb = g_v + (size_t)bh * T_ * HS_;

    float qreg[64];
#pragma unroll
    for (int d4 = 0; d4 < 16; d4++) {
        float4 v = *(const float4*)(qb + (size_t)qrow * HS_ + d4 * 4);
        qreg[d4 * 4 + 0] = v.x * 0.125f;   // HS^-0.5
        qreg[d4 * 4 + 1] = v.y * 0.125f;
        qreg[d4 * 4 + 2] = v.z * 0.125f;
        qreg[d4 * 4 + 3] = v.w * 0.125f;
    }

    float o[64];
#pragma unroll
    for (int d = 0; d < 64; d++) o[d] = 0.f;
    float mrow = -1e30f;
    float lrow = 0.f;

    __shared__ float Ks[64][64];
    __shared__ float Vs[64][64];

    for (int kt = 0; kt <= qt; kt++) {
        const int k0 = kt * 64;
        __syncthreads();   // previous iteration's Ks/Vs reads done
#pragma unroll
        for (int it = 0; it < 16; it++) {
            int l = it * 64 + tid;            // float4 linear index
            int r = l >> 4;
            int c = (l & 15) * 4;
            *(float4*)&Ks[r][c] = *(const float4*)(kb + (size_t)(k0 + r) * HS_ + c);
            *(float4*)&Vs[r][c] = *(const float4*)(vb + (size_t)(k0 + r) * HS_ + c);
        }
        __syncthreads();

        const bool lastTile = (kt == qt);

#pragma unroll 1
        for (int jc = 0; jc < 4; jc++) {
            const int jbase = jc * 16;
            float s[16];
#pragma unroll
            for (int jj = 0; jj < 16; jj++) {
                float a = 0.f;
#pragma unroll
                for (int d4 = 0; d4 < 16; d4++) {
                    float4 kv = *(const float4*)&Ks[jbase + jj][d4 * 4];
                    a += qreg[d4 * 4 + 0] * kv.x;
                    a += qreg[d4 * 4 + 1] * kv.y;
                    a += qreg[d4 * 4 + 2] * kv.z;
                    a += qreg[d4 * 4 + 3] * kv.w;
                }
                s[jj] = a;
            }
            if (lastTile) {
#pragma unroll
                for (int jj = 0; jj < 16; jj++)
                    if (k0 + jbase + jj > qrow) s[jj] = -1e30f;
            }
            // online softmax update
            float mn = mrow;
#pragma unroll
            for (int jj = 0; jj < 16; jj++) mn = fmaxf(mn, s[jj]);
            float corr = __expf(mrow - mn);
            mrow = mn;
            lrow *= corr;
#pragma unroll
            for (int d = 0; d < 64; d++) o[d] *= corr;
            float p[16];
#pragma unroll
            for (int jj = 0; jj < 16; jj++) {
                p[jj] = __expf(s[jj] - mn);
                lrow += p[jj];
            }
            // O += P * V
#pragma unroll
            for (int jj = 0; jj < 16; jj++) {
#pragma unroll
                for (int d4 = 0; d4 < 16; d4++) {
                    float4 vv = *(const float4*)&Vs[jbase + jj][d4 * 4];
                    o[d4 * 4 + 0] += p[jj] * vv.x;
                    o[d4 * 4 + 1] += p[jj] * vv.y;
                    o[d4 * 4 + 2] += p[jj] * vv.z;
                    o[d4 * 4 + 3] += p[jj] * vv.w;
                }
            }
        }
    }

    const float inv = 1.0f / lrow;
    const int b = bh >> 4;
    const int h = bh & (H_ - 1);
    float* dst = g_att + ((size_t)b * T_ + qrow) * C_ + h * HS_;
#pragma unroll
    for (int d4 = 0; d4 < 16; d4++) {
        float4 v;
        v.x = o[d4 * 4 + 0] * inv;
        v.y = o[d4 * 4 + 1] * inv;
        v.z = o[d4 * 4 + 2] * inv;
        v.w = o[d4 * 4 + 3] * inv;
        *(float4*)(dst + d4 * 4) = v;
    }
}

// ---------------------------------------------------------------------------
// Output projection: out[m,n] = sum_k g_att[m,k] * Wp[k,n] + bp[n]
// M=4096, N=1024, K=1024. Same 128x128x8 tiling.
// ---------------------------------------------------------------------------
__global__ __launch_bounds__(256) void out_gemm(
    const float* __restrict__ Wp,
    const float* __restrict__ bp,
    float* __restrict__ out)
{
    __shared__ float As[8][128];
    __shared__ float Bs[8][128];

    const int tid = threadIdx.x;
    const int m0 = blockIdx.y * 128;
    const int n0 = blockIdx.x * 128;
    const int tx = tid & 15;
    const int ty = tid >> 4;

    const int arow = tid >> 1;
    const int akk  = (tid & 1) * 4;
    const float* Aptr = g_att + (size_t)(m0 + arow) * C_ + akk;

    const int bln = (tid & 31) * 4;
    const int bkk = tid >> 5;

    float acc[8][8];
#pragma unroll
    for (int i = 0; i < 8; i++)
#pragma unroll
        for (int j = 0; j < 8; j++) acc[i][j] = 0.f;

    for (int k0 = 0; k0 < C_; k0 += 8) {
        float4 av = *(const float4*)(Aptr + k0);
        As[akk + 0][arow] = av.x;
        As[akk + 1][arow] = av.y;
        As[akk + 2][arow] = av.z;
        As[akk + 3][arow] = av.w;
        *(float4*)&Bs[bkk][bln] =
            *(const float4*)(Wp + (size_t)(k0 + bkk) * C_ + n0 + bln);
        __syncthreads();
#pragma unroll
        for (int kk = 0; kk < 8; kk++) {
            float a[8], b[8];
            *(float4*)&a[0] = *(const float4*)&As[kk][ty * 8];
            *(float4*)&a[4] = *(const float4*)&As[kk][ty * 8 + 4];
            *(float4*)&b[0] = *(const float4*)&Bs[kk][tx * 8];
            *(float4*)&b[4] = *(const float4*)&Bs[kk][tx * 8 + 4];
#pragma unroll
            for (int i = 0; i < 8; i++)
#pragma unroll
                for (int j = 0; j < 8; j++)
                    acc[i][j] += a[i] * b[j];
        }
        __syncthreads();
    }

#pragma unroll
    for (int i = 0; i < 8; i++) {
        int m = m0 + ty * 8 + i;
#pragma unroll
        for (int j = 0; j < 8; j++) {
            int n = n0 + tx * 8 + j;
            out[(size_t)m * C_ + n] = acc[i][j] + bp[n];
        }
    }
}

// ---------------------------------------------------------------------------
extern "C" void kernel_launch(void* const* d_in, const int* in_sizes, int n_in,
                              void* d_out, int out_size)
{
    const float* x  = (const float*)d_in[0];
    const float* Wq = (const float*)d_in[1];
    const float* Wk = (const float*)d_in[2];
    const float* Wv = (const float*)d_in[3];
    const float* Wp = (const float*)d_in[4];
    const float* bp = (const float*)d_in[5];
    float* out = (float*)d_out;

    // 1) QKV projection: M=4096, N=3072
    qkv_gemm<<<dim3(3072 / 128, BT_ / 128), 256>>>(x, Wq, Wk, Wv);
    // 2) Causal flash attention: (T/64 query tiles, B*H heads)
    flash_attn<<<dim3(T_ / 64, B_ * H_), 64>>>();
    // 3) Output projection + bias: M=4096, N=1024
    out_gemm<<<dim3(C_ / 128, BT_ / 128), 256>>>(Wp, bp, out);
}

// round 3
// speedup vs baseline: 1.6813x; 1.6813x over previous
#include <cuda_runtime.h>
#include <cstdint>

#define H_  16
#define HS_ 64
#define C_  1024
#define T_  2048
#define B_  2
#define BT_ (B_ * T_)   // 4096

// ---------------------------------------------------------------------------
// Scratch (no device allocation allowed)
// ---------------------------------------------------------------------------
__device__ float g_q[B_ * H_ * T_ * HS_];
__device__ float g_k[B_ * H_ * T_ * HS_];
__device__ float g_v[B_ * H_ * T_ * HS_];
__device__ float g_att[BT_ * C_];
__device__ float g_bt[3 * H_ * HS_ * C_];   // K-major QKV weights: [3072][1024]
__device__ float g_wpt[C_ * C_];            // K-major Wp: [n][k]

// ---------------------------------------------------------------------------
__device__ __forceinline__ uint32_t f2tf32(float f) {
    uint32_t r;
    asm("cvt.rna.tf32.f32 %0, %1;" : "=r"(r) : "f"(f));
    return r;
}
__device__ __forceinline__ void mma_tf32(float c[4], const uint32_t a[4],
                                         const uint32_t b[2]) {
    asm volatile(
        "mma.sync.aligned.m16n8k8.row.col.f32.tf32.tf32.f32 "
        "{%0,%1,%2,%3}, {%4,%5,%6,%7}, {%8,%9}, {%0,%1,%2,%3};"
        : "+f"(c[0]), "+f"(c[1]), "+f"(c[2]), "+f"(c[3])
        : "r"(a[0]), "r"(a[1]), "r"(a[2]), "r"(a[3]), "r"(b[0]), "r"(b[1]));
}

// ---------------------------------------------------------------------------
// Weight transposes into K-major scratch
// ---------------------------------------------------------------------------
__global__ void transpose_w(const float* __restrict__ Wq,
                            const float* __restrict__ Wk,
                            const float* __restrict__ Wv)
{
    __shared__ float tile[32][33];
    const int which = blockIdx.z >> 4;         // 0..2
    const int h     = blockIdx.z & 15;
    const float* W  = (which == 0) ? Wq : (which == 1) ? Wk : Wv;
    const int c0 = blockIdx.x * 32;
    const int d0 = blockIdx.y * 32;
    const int tx = threadIdx.x, ty = threadIdx.y;
#pragma unroll
    for (int j = 0; j < 32; j += 8)
        tile[ty + j][tx] = W[h * (C_ * HS_) + (c0 + ty + j) * HS_ + d0 + tx];
    __syncthreads();
    float* out = g_bt + (size_t)(which * 1024 + h * HS_ + d0) * C_ + c0;
#pragma unroll
    for (int j = 0; j < 32; j += 8)
        out[(ty + j) * C_ + tx] = tile[tx][ty + j];
}

__global__ void transpose_wp(const float* __restrict__ Wp)
{
    __shared__ float tile[32][33];
    const int k0 = blockIdx.x * 32;
    const int n0 = blockIdx.y * 32;
    const int tx = threadIdx.x, ty = threadIdx.y;
#pragma unroll
    for (int j = 0; j < 32; j += 8)
        tile[ty + j][tx] = Wp[(k0 + ty + j) * C_ + n0 + tx];
    __syncthreads();
#pragma unroll
    for (int j = 0; j < 32; j += 8)
        g_wpt[(size_t)(n0 + ty + j) * C_ + k0 + tx] = tile[tx][ty + j];
}

// ---------------------------------------------------------------------------
// tf32 mma.sync GEMM mainloop: 128x128 block tile, K in 32-chunks.
// A row-major [*,1024] at m0. Bt K-major [*,1024] at n0 (row n, col k).
// acc[mt][nt][4] per warp (warp tile 64x32 = 4x4 m16n8k8).
// ---------------------------------------------------------------------------
struct GemmCtx {
    int m0, n0, wm, wn, g, t4;
};

__device__ __forceinline__ void gemm_core(
    const float* __restrict__ A, const float* __restrict__ Bt,
    int m0, int n0, float acc[4][4][4],
    uint32_t (*As)[36], uint32_t (*Bs)[36])
{
    const int tid  = threadIdx.x;
    const int wid  = tid >> 5;
    const int lane = tid & 31;
    const int wm = (wid & 1) * 64;
    const int wn = (wid >> 1) * 32;
    const int g  = lane >> 2;
    const int t4 = lane & 3;

    const int lrow = tid >> 3;        // 0..31, + p*32
    const int lc4  = (tid & 7) * 4;   // k-col (floats)

    const float* Ap = A + (size_t)(m0 + lrow) * C_ + lc4;
    const float* Bp = Bt + (size_t)(n0 + lrow) * C_ + lc4;

#pragma unroll
    for (int mt = 0; mt < 4; mt++)
#pragma unroll
        for (int nt = 0; nt < 4; nt++)
#pragma unroll
            for (int i = 0; i < 4; i++) acc[mt][nt][i] = 0.f;

#pragma unroll 1
    for (int k0 = 0; k0 < C_; k0 += 32) {
        // stage A/B chunk (128 rows x 32 k) as tf32
#pragma unroll
        for (int p = 0; p < 4; p++) {
            float4 va = *(const float4*)(Ap + k0 + (size_t)p * 32 * C_);
            uint4 ta = {f2tf32(va.x), f2tf32(va.y), f2tf32(va.z), f2tf32(va.w)};
            *(uint4*)&As[lrow + p * 32][lc4] = ta;
            float4 vb = *(const float4*)(Bp + k0 + (size_t)p * 32 * C_);
            uint4 tb = {f2tf32(vb.x), f2tf32(vb.y), f2tf32(vb.z), f2tf32(vb.w)};
            *(uint4*)&Bs[lrow + p * 32][lc4] = tb;
        }
        __syncthreads();

#pragma unroll
        for (int ks = 0; ks < 4; ks++) {
            const int k = ks * 8;
            uint32_t af[4][4], bf[4][2];
#pragma unroll
            for (int mt = 0; mt < 4; mt++) {
                const int r = wm + mt * 16 + g;
                af[mt][0] = As[r][k + t4];
                af[mt][1] = As[r + 8][k + t4];
                af[mt][2] = As[r][k + t4 + 4];
                af[mt][3] = As[r + 8][k + t4 + 4];
            }
#pragma unroll
            for (int nt = 0; nt < 4; nt++) {
                const int n = wn + nt * 8 + g;
                bf[nt][0] = Bs[n][k + t4];
                bf[nt][1] = Bs[n][k + t4 + 4];
            }
#pragma unroll
            for (int mt = 0; mt < 4; mt++)
#pragma unroll
                for (int nt = 0; nt < 4; nt++)
                    mma_tf32(acc[mt][nt], af[mt], bf[nt]);
        }
        __syncthreads();
    }
}

// ---------------------------------------------------------------------------
// QKV projection: M=4096 (b,t), N=3072 (qkv,h,d), K=1024
// ---------------------------------------------------------------------------
__global__ __launch_bounds__(256) void qkv_gemm_mma(const float* __restrict__ x)
{
    __shared__ uint32_t As[128][36];
    __shared__ uint32_t Bs[128][36];
    const int m0 = blockIdx.y * 128;
    const int n0 = blockIdx.x * 128;

    float acc[4][4][4];
    gemm_core(x, g_bt, m0, n0, acc, As, Bs);

    const int tid  = threadIdx.x;
    const int wid  = tid >> 5;
    const int lane = tid & 31;
    const int wm = (wid & 1) * 64;
    const int wn = (wid >> 1) * 32;
    const int g  = lane >> 2;
    const int t4 = lane & 3;

#pragma unroll
    for (int mt = 0; mt < 4; mt++) {
#pragma unroll
        for (int nt = 0; nt < 4; nt++) {
            const int n  = n0 + wn + nt * 8 + t4 * 2;
            const int qk = n >> 10;
            const int h2 = (n >> 6) & (H_ - 1);
            const int d2 = n & (HS_ - 1);
            float* base = ((qk == 0) ? g_q : (qk == 1) ? g_k : g_v);
#pragma unroll
            for (int half = 0; half < 2; half++) {
                const int m = m0 + wm + mt * 16 + g + half * 8;
                const int b = m >> 11;
                const int t = m & (T_ - 1);
                float2 v;
                v.x = acc[mt][nt][half * 2 + 0];
                v.y = acc[mt][nt][half * 2 + 1];
                *(float2*)&base[(((size_t)b * H_ + h2) * T_ + t) * HS_ + d2] = v;
            }
        }
    }
}

// ---------------------------------------------------------------------------
// Output projection: M=4096, N=1024, K=1024, + bias
// ---------------------------------------------------------------------------
__global__ __launch_bounds__(256) void out_gemm_mma(const float* __restrict__ bp,
                                                    float* __restrict__ out)
{
    __shared__ uint32_t As[128][36];
    __shared__ uint32_t Bs[128][36];
    const int m0 = blockIdx.y * 128;
    const int n0 = blockIdx.x * 128;

    float acc[4][4][4];
    gemm_core(g_att, g_wpt, m0, n0, acc, As, Bs);

    const int tid  = threadIdx.x;
    const int wid  = tid >> 5;
    const int lane = tid & 31;
    const int wm = (wid & 1) * 64;
    const int wn = (wid >> 1) * 32;
    const int g  = lane >> 2;
    const int t4 = lane & 3;

#pragma unroll
    for (int mt = 0; mt < 4; mt++) {
#pragma unroll
        for (int nt = 0; nt < 4; nt++) {
            const int n = n0 + wn + nt * 8 + t4 * 2;
            const float2 bias = *(const float2*)(bp + n);
#pragma unroll
            for (int half = 0; half < 2; half++) {
                const int m = m0 + wm + mt * 16 + g + half * 8;
                float2 v;
                v.x = acc[mt][nt][half * 2 + 0] + bias.x;
                v.y = acc[mt][nt][half * 2 + 1] + bias.y;
                *(float2*)&out[(size_t)m * C_ + n] = v;
            }
        }
    }
}

// ---------------------------------------------------------------------------
// Flash attention, fp32, causal (unchanged from R1 baseline).
// ---------------------------------------------------------------------------
__global__ __launch_bounds__(64) void flash_attn()
{
    const int qt  = blockIdx.x;
    const int bh  = blockIdx.y;
    const int tid = threadIdx.x;
    const int q0   = qt * 64;
    const int qrow = q0 + tid;

    const float* qb = g_q + (size_t)bh * T_ * HS_;
    const float* kb = g_k + (size_t)bh * T_ * HS_;
    const float* vb = g_v + (size_t)bh * T_ * HS_;

    float qreg[64];
#pragma unroll
    for (int d4 = 0; d4 < 16; d4++) {
        float4 v = *(const float4*)(qb + (size_t)qrow * HS_ + d4 * 4);
        qreg[d4 * 4 + 0] = v.x * 0.125f;
        qreg[d4 * 4 + 1] = v.y * 0.125f;
        qreg[d4 * 4 + 2] = v.z * 0.125f;
        qreg[d4 * 4 + 3] = v.w * 0.125f;
    }

    float o[64];
#pragma unroll
    for (int d = 0; d < 64; d++) o[d] = 0.f;
    float mrow = -1e30f;
    float lrow = 0.f;

    __shared__ float Ks[64][64];
    __shared__ float Vs[64][64];

    for (int kt = 0; kt <= qt; kt++) {
        const int k0 = kt * 64;
        __syncthreads();
#pragma unroll
        for (int it = 0; it < 16; it++) {
            int l = it * 64 + tid;
            int r = l >> 4;
            int c = (l & 15) * 4;
            *(float4*)&Ks[r][c] = *(const float4*)(kb + (size_t)(k0 + r) * HS_ + c);
            *(float4*)&Vs[r][c] = *(const float4*)(vb + (size_t)(k0 + r) * HS_ + c);
        }
        __syncthreads();

        const bool lastTile = (kt == qt);

#pragma unroll 1
        for (int jc = 0; jc < 4; jc++) {
            const int jbase = jc * 16;
            float s[16];
#pragma unroll
            for (int jj = 0; jj < 16; jj++) {
                float a = 0.f;
#pragma unroll
                for (int d4 = 0; d4 < 16; d4++) {
                    float4 kv = *(const float4*)&Ks[jbase + jj][d4 * 4];
                    a += qreg[d4 * 4 + 0] * kv.x;
                    a += qreg[d4 * 4 + 1] * kv.y;
                    a += qreg[d4 * 4 + 2] * kv.z;
                    a += qreg[d4 * 4 + 3] * kv.w;
                }
                s[jj] = a;
            }
            if (lastTile) {
#pragma unroll
                for (int jj = 0; jj < 16; jj++)
                    if (k0 + jbase + jj > qrow) s[jj] = -1e30f;
            }
            float mn = mrow;
#pragma unroll
            for (int jj = 0; jj < 16; jj++) mn = fmaxf(mn, s[jj]);
            float corr = __expf(mrow - mn);
            mrow = mn;
            lrow *= corr;
#pragma unroll
            for (int d = 0; d < 64; d++) o[d] *= corr;
            float p[16];
#pragma unroll
            for (int jj = 0; jj < 16; jj++) {
                p[jj] = __expf(s[jj] - mn);
                lrow += p[jj];
            }
#pragma unroll
            for (int jj = 0; jj < 16; jj++) {
#pragma unroll
                for (int d4 = 0; d4 < 16; d4++) {
                    float4 vv = *(const float4*)&Vs[jbase + jj][d4 * 4];
                    o[d4 * 4 + 0] += p[jj] * vv.x;
                    o[d4 * 4 + 1] += p[jj] * vv.y;
                    o[d4 * 4 + 2] += p[jj] * vv.z;
                    o[d4 * 4 + 3] += p[jj] * vv.w;
                }
            }
        }
    }

    const float inv = 1.0f / lrow;
    const int b = bh >> 4;
    const int h = bh & (H_ - 1);
    float* dst = g_att + ((size_t)b * T_ + qrow) * C_ + h * HS_;
#pragma unroll
    for (int d4 = 0; d4 < 16; d4++) {
        float4 v;
        v.x = o[d4 * 4 + 0] * inv;
        v.y = o[d4 * 4 + 1] * inv;
        v.z = o[d4 * 4 + 2] * inv;
        v.w = o[d4 * 4 + 3] * inv;
        *(float4*)(dst + d4 * 4) = v;
    }
}

// ---------------------------------------------------------------------------
extern "C" void kernel_launch(void* const* d_in, const int* in_sizes, int n_in,
                              void* d_out, int out_size)
{
    const float* x  = (const float*)d_in[0];
    const float* Wq = (const float*)d_in[1];
    const float* Wk = (const float*)d_in[2];
    const float* Wv = (const float*)d_in[3];
    const float* Wp = (const float*)d_in[4];
    const float* bp = (const float*)d_in[5];
    float* out = (float*)d_out;

    // 0) weight transposes into K-major scratch
    transpose_w<<<dim3(C_ / 32, HS_ / 32, 3 * H_), dim3(32, 8)>>>(Wq, Wk, Wv);
    transpose_wp<<<dim3(C_ / 32, C_ / 32), dim3(32, 8)>>>(Wp);
    // 1) QKV projection (tensor, mma.sync tf32): M=4096, N=3072
    qkv_gemm_mma<<<dim3(3072 / 128, BT_ / 128), 256>>>(x);
    // 2) Causal flash attention (SIMT fp32, unchanged)
    flash_attn<<<dim3(T_ / 64, B_ * H_), 64>>>();
    // 3) Output projection + bias (tensor, mma.sync tf32): M=4096, N=1024
    out_gemm_mma<<<dim3(C_ / 128, BT_ / 128), 256>>>(bp, out);
}

// round 5
// speedup vs baseline: 4.4143x; 2.6255x over previous
#include <cuda_runtime.h>
#include <cstdint>

#define H_  16
#define HS_ 64
#define C_  1024
#define T_  2048
#define B_  2
#define BT_ (B_ * T_)   // 4096
#define LOG2E 1.4426950408889634f

// ---------------------------------------------------------------------------
// Scratch (no device allocation allowed)
// ---------------------------------------------------------------------------
__device__ float g_q[B_ * H_ * T_ * HS_];
__device__ float g_k[B_ * H_ * T_ * HS_];
__device__ float g_v[B_ * H_ * T_ * HS_];
__device__ float g_att[BT_ * C_];
__device__ float g_bt[3 * H_ * HS_ * C_];   // K-major QKV weights: [3072][1024]
__device__ float g_wpt[C_ * C_];            // K-major Wp: [n][k]

// ---------------------------------------------------------------------------
__device__ __forceinline__ uint32_t f2tf32(float f) {
    uint32_t r;
    asm("cvt.rna.tf32.f32 %0, %1;" : "=r"(r) : "f"(f));
    return r;
}
__device__ __forceinline__ float ex2f(float x) {
    float y;
    asm("ex2.approx.f32 %0, %1;" : "=f"(y) : "f"(x));
    return y;
}
__device__ __forceinline__ void mma_tf32(float c[4], const uint32_t a[4],
                                         const uint32_t b[2]) {
    asm volatile(
        "mma.sync.aligned.m16n8k8.row.col.f32.tf32.tf32.f32 "
        "{%0,%1,%2,%3}, {%4,%5,%6,%7}, {%8,%9}, {%0,%1,%2,%3};"
        : "+f"(c[0]), "+f"(c[1]), "+f"(c[2]), "+f"(c[3])
        : "r"(a[0]), "r"(a[1]), "r"(a[2]), "r"(a[3]), "r"(b[0]), "r"(b[1]));
}

// ---------------------------------------------------------------------------
// Weight transposes into K-major scratch
// ---------------------------------------------------------------------------
__global__ void transpose_w(const float* __restrict__ Wq,
                            const float* __restrict__ Wk,
                            const float* __restrict__ Wv)
{
    __shared__ float tile[32][33];
    const int which = blockIdx.z >> 4;         // 0..2
    const int h     = blockIdx.z & 15;
    const float* W  = (which == 0) ? Wq : (which == 1) ? Wk : Wv;
    const int c0 = blockIdx.x * 32;
    const int d0 = blockIdx.y * 32;
    const int tx = threadIdx.x, ty = threadIdx.y;
#pragma unroll
    for (int j = 0; j < 32; j += 8)
        tile[ty + j][tx] = W[h * (C_ * HS_) + (c0 + ty + j) * HS_ + d0 + tx];
    __syncthreads();
    float* out = g_bt + (size_t)(which * 1024 + h * HS_ + d0) * C_ + c0;
#pragma unroll
    for (int j = 0; j < 32; j += 8)
        out[(ty + j) * C_ + tx] = tile[tx][ty + j];
}

__global__ void transpose_wp(const float* __restrict__ Wp)
{
    __shared__ float tile[32][33];
    const int k0 = blockIdx.x * 32;
    const int n0 = blockIdx.y * 32;
    const int tx = threadIdx.x, ty = threadIdx.y;
#pragma unroll
    for (int j = 0; j < 32; j += 8)
        tile[ty + j][tx] = Wp[(k0 + ty + j) * C_ + n0 + tx];
    __syncthreads();
#pragma unroll
    for (int j = 0; j < 32; j += 8)
        g_wpt[(size_t)(n0 + ty + j) * C_ + k0 + tx] = tile[tx][ty + j];
}

// ---------------------------------------------------------------------------
// tf32 mma.sync GEMM mainloop: 128x128 block tile, K in 32-chunks.
// ---------------------------------------------------------------------------
__device__ __forceinline__ void gemm_core(
    const float* __restrict__ A, const float* __restrict__ Bt,
    int m0, int n0, float acc[4][4][4],
    uint32_t (*As)[36], uint32_t (*Bs)[36])
{
    const int tid  = threadIdx.x;
    const int wid  = tid >> 5;
    const int lane = tid & 31;
    const int wm = (wid & 1) * 64;
    const int wn = (wid >> 1) * 32;
    const int g  = lane >> 2;
    const int t4 = lane & 3;

    const int lrow = tid >> 3;        // 0..31, + p*32
    const int lc4  = (tid & 7) * 4;   // k-col (floats)

    const float* Ap = A + (size_t)(m0 + lrow) * C_ + lc4;
    const float* Bp = Bt + (size_t)(n0 + lrow) * C_ + lc4;

#pragma unroll
    for (int mt = 0; mt < 4; mt++)
#pragma unroll
        for (int nt = 0; nt < 4; nt++)
#pragma unroll
            for (int i = 0; i < 4; i++) acc[mt][nt][i] = 0.f;

#pragma unroll 1
    for (int k0 = 0; k0 < C_; k0 += 32) {
#pragma unroll
        for (int p = 0; p < 4; p++) {
            float4 va = *(const float4*)(Ap + k0 + (size_t)p * 32 * C_);
            uint4 ta = {f2tf32(va.x), f2tf32(va.y), f2tf32(va.z), f2tf32(va.w)};
            *(uint4*)&As[lrow + p * 32][lc4] = ta;
            float4 vb = *(const float4*)(Bp + k0 + (size_t)p * 32 * C_);
            uint4 tb = {f2tf32(vb.x), f2tf32(vb.y), f2tf32(vb.z), f2tf32(vb.w)};
            *(uint4*)&Bs[lrow + p * 32][lc4] = tb;
        }
        __syncthreads();

#pragma unroll
        for (int ks = 0; ks < 4; ks++) {
            const int k = ks * 8;
            uint32_t af[4][4], bf[4][2];
#pragma unroll
            for (int mt = 0; mt < 4; mt++) {
                const int r = wm + mt * 16 + g;
                af[mt][0] = As[r][k + t4];
                af[mt][1] = As[r + 8][k + t4];
                af[mt][2] = As[r][k + t4 + 4];
                af[mt][3] = As[r + 8][k + t4 + 4];
            }
#pragma unroll
            for (int nt = 0; nt < 4; nt++) {
                const int n = wn + nt * 8 + g;
                bf[nt][0] = Bs[n][k + t4];
                bf[nt][1] = Bs[n][k + t4 + 4];
            }
#pragma unroll
            for (int mt = 0; mt < 4; mt++)
#pragma unroll
                for (int nt = 0; nt < 4; nt++)
                    mma_tf32(acc[mt][nt], af[mt], bf[nt]);
        }
        __syncthreads();
    }
}

// ---------------------------------------------------------------------------
// QKV projection: M=4096 (b,t), N=3072 (qkv,h,d), K=1024
// ---------------------------------------------------------------------------
__global__ __launch_bounds__(256) void qkv_gemm_mma(const float* __restrict__ x)
{
    __shared__ uint32_t As[128][36];
    __shared__ uint32_t Bs[128][36];
    const int m0 = blockIdx.y * 128;
    const int n0 = blockIdx.x * 128;

    float acc[4][4][4];
    gemm_core(x, g_bt, m0, n0, acc, As, Bs);

    const int tid  = threadIdx.x;
    const int wid  = tid >> 5;
    const int lane = tid & 31;
    const int wm = (wid & 1) * 64;
    const int wn = (wid >> 1) * 32;
    const int g  = lane >> 2;
    const int t4 = lane & 3;

#pragma unroll
    for (int mt = 0; mt < 4; mt++) {
#pragma unroll
        for (int nt = 0; nt < 4; nt++) {
            const int n  = n0 + wn + nt * 8 + t4 * 2;
            const int qk = n >> 10;
            const int h2 = (n >> 6) & (H_ - 1);
            const int d2 = n & (HS_ - 1);
            float* base = ((qk == 0) ? g_q : (qk == 1) ? g_k : g_v);
#pragma unroll
            for (int half = 0; half < 2; half++) {
                const int m = m0 + wm + mt * 16 + g + half * 8;
                const int b = m >> 11;
                const int t = m & (T_ - 1);
                float2 v;
                v.x = acc[mt][nt][half * 2 + 0];
                v.y = acc[mt][nt][half * 2 + 1];
                *(float2*)&base[(((size_t)b * H_ + h2) * T_ + t) * HS_ + d2] = v;
            }
        }
    }
}

// ---------------------------------------------------------------------------
// Output projection: M=4096, N=1024, K=1024, + bias
// ---------------------------------------------------------------------------
__global__ __launch_bounds__(256) void out_gemm_mma(const float* __restrict__ bp,
                                                    float* __restrict__ out)
{
    __shared__ uint32_t As[128][36];
    __shared__ uint32_t Bs[128][36];
    const int m0 = blockIdx.y * 128;
    const int n0 = blockIdx.x * 128;

    float acc[4][4][4];
    gemm_core(g_att, g_wpt, m0, n0, acc, As, Bs);

    const int tid  = threadIdx.x;
    const int wid  = tid >> 5;
    const int lane = tid & 31;
    const int wm = (wid & 1) * 64;
    const int wn = (wid >> 1) * 32;
    const int g  = lane >> 2;
    const int t4 = lane & 3;

#pragma unroll
    for (int mt = 0; mt < 4; mt++) {
#pragma unroll
        for (int nt = 0; nt < 4; nt++) {
            const int n = n0 + wn + nt * 8 + t4 * 2;
            const float2 bias = *(const float2*)(bp + n);
#pragma unroll
            for (int half = 0; half < 2; half++) {
                const int m = m0 + wm + mt * 16 + g + half * 8;
                float2 v;
                v.x = acc[mt][nt][half * 2 + 0] + bias.x;
                v.y = acc[mt][nt][half * 2 + 1] + bias.y;
                *(float2*)&out[(size_t)m * C_ + n] = v;
            }
        }
    }
}

// ---------------------------------------------------------------------------
// Flash attention with tf32 mma.sync. One block = 64 q rows of one (b,h).
// 4 warps; warp w owns the 16-row stripe [w*16, w*16+16).
// S = Q K^T and O += P V both on tensor pipe; softmax in base-2 domain.
// SMEM (uint32 tf32 values): QP[64][68] (Q then P stripes), Ks[64][68], Vs[64][72]
// ---------------------------------------------------------------------------
#define FA_SMEM_U32 (64 * 68 * 2 + 64 * 72)

__global__ __launch_bounds__(128) void flash_mma()
{
    extern __shared__ uint32_t sm[];
    uint32_t* QP = sm;                    // [64][68]
    uint32_t* Ks = sm + 64 * 68;          // [64][68]
    uint32_t* Vs = sm + 2 * 64 * 68;      // [64][72]

    const int qt  = gridDim.x - 1 - blockIdx.x;   // long blocks first
    const int bh  = blockIdx.y;
    const int tid = threadIdx.x;
    const int wid = tid >> 5, lane = tid & 31;
    const int g = lane >> 2, t4 = lane & 3;
    const int wr = wid * 16;
    const int q0 = qt * 64;

    const float* qb = g_q + (size_t)bh * T_ * HS_;
    const float* kb = g_k + (size_t)bh * T_ * HS_;
    const float* vb = g_v + (size_t)bh * T_ * HS_;

    // stage Q (scale folded: 1/sqrt(HS) * log2(e)), tf32
    const float qscale = 0.125f * LOG2E;
#pragma unroll
    for (int it = 0; it < 8; it++) {
        int l = it * 128 + tid, r = l >> 4, c4 = (l & 15) * 4;
        float4 v = *(const float4*)(qb + (size_t)(q0 + r) * HS_ + c4);
        uint32_t* d = &QP[r * 68 + c4];
        d[0] = f2tf32(v.x * qscale); d[1] = f2tf32(v.y * qscale);
        d[2] = f2tf32(v.z * qscale); d[3] = f2tf32(v.w * qscale);
    }
    __syncthreads();

    uint32_t qa[8][4];
#pragma unroll
    for (int kk = 0; kk < 8; kk++) {
        qa[kk][0] = QP[(wr + g) * 68 + t4 + 8 * kk];
        qa[kk][1] = QP[(wr + g + 8) * 68 + t4 + 8 * kk];
        qa[kk][2] = QP[(wr + g) * 68 + t4 + 4 + 8 * kk];
        qa[kk][3] = QP[(wr + g + 8) * 68 + t4 + 4 + 8 * kk];
    }
    // QP now reused as per-warp P stripes (each warp only touches its own rows)

    float oacc[8][4];
#pragma unroll
    for (int nt = 0; nt < 8; nt++)
#pragma unroll
        for (int i = 0; i < 4; i++) oacc[nt][i] = 0.f;
    float m0 = -1e30f, m1 = -1e30f, l0 = 0.f, l1 = 0.f;

#pragma unroll 1
    for (int kt = 0; kt <= qt; kt++) {
        const int k0 = kt * 64;
        __syncthreads();   // prior iteration's Ks/Vs consumers done
#pragma unroll
        for (int it = 0; it < 8; it++) {
            int l = it * 128 + tid, r = l >> 4, c4 = (l & 15) * 4;
            float4 kv = *(const float4*)(kb + (size_t)(k0 + r) * HS_ + c4);
            uint32_t* dk = &Ks[r * 68 + c4];
            dk[0] = f2tf32(kv.x); dk[1] = f2tf32(kv.y);
            dk[2] = f2tf32(kv.z); dk[3] = f2tf32(kv.w);
            float4 vv = *(const float4*)(vb + (size_t)(k0 + r) * HS_ + c4);
            uint32_t* dv = &Vs[r * 72 + c4];
            dv[0] = f2tf32(vv.x); dv[1] = f2tf32(vv.y);
            dv[2] = f2tf32(vv.z); dv[3] = f2tf32(vv.w);
        }
        __syncthreads();

        // S = Q K^T  (units: log2)
        float sacc[8][4];
#pragma unroll
        for (int nt = 0; nt < 8; nt++)
#pragma unroll
            for (int i = 0; i < 4; i++) sacc[nt][i] = 0.f;
#pragma unroll
        for (int kk = 0; kk < 8; kk++) {
#pragma unroll
            for (int nt = 0; nt < 8; nt++) {
                uint32_t bf[2];
                bf[0] = Ks[(g + 8 * nt) * 68 + t4 + 8 * kk];
                bf[1] = Ks[(g + 8 * nt) * 68 + t4 + 4 + 8 * kk];
                mma_tf32(sacc[nt], qa[kk], bf);
            }
        }

        if (kt == qt) {   // causal mask on the diagonal tile (local coords)
            const int r0 = wr + g, r1 = wr + g + 8;
#pragma unroll
            for (int nt = 0; nt < 8; nt++) {
                const int c = 8 * nt + 2 * t4;
                if (c     > r0) sacc[nt][0] = -1e30f;
                if (c + 1 > r0) sacc[nt][1] = -1e30f;
                if (c     > r1) sacc[nt][2] = -1e30f;
                if (c + 1 > r1) sacc[nt][3] = -1e30f;
            }
        }

        // online softmax (base 2)
        float ml0 = -1e30f, ml1 = -1e30f;
#pragma unroll
        for (int nt = 0; nt < 8; nt++) {
            ml0 = fmaxf(ml0, fmaxf(sacc[nt][0], sacc[nt][1]));
            ml1 = fmaxf(ml1, fmaxf(sacc[nt][2], sacc[nt][3]));
        }
        ml0 = fmaxf(ml0, __shfl_xor_sync(0xffffffffu, ml0, 1));
        ml0 = fmaxf(ml0, __shfl_xor_sync(0xffffffffu, ml0, 2));
        ml1 = fmaxf(ml1, __shfl_xor_sync(0xffffffffu, ml1, 1));
        ml1 = fmaxf(ml1, __shfl_xor_sync(0xffffffffu, ml1, 2));
        const float mn0 = fmaxf(m0, ml0), mn1 = fmaxf(m1, ml1);
        const float corr0 = ex2f(m0 - mn0), corr1 = ex2f(m1 - mn1);
        m0 = mn0; m1 = mn1;

        float ps0 = 0.f, ps1 = 0.f;
#pragma unroll
        for (int nt = 0; nt < 8; nt++) {
            float p00 = ex2f(sacc[nt][0] - mn0);
            float p01 = ex2f(sacc[nt][1] - mn0);
            float p10 = ex2f(sacc[nt][2] - mn1);
            float p11 = ex2f(sacc[nt][3] - mn1);
            ps0 += p00 + p01;
            ps1 += p10 + p11;
            uint2 st0 = {f2tf32(p00), f2tf32(p01)};
            *(uint2*)&QP[(wr + g) * 68 + 8 * nt + 2 * t4] = st0;
            uint2 st1 = {f2tf32(p10), f2tf32(p11)};
            *(uint2*)&QP[(wr + g + 8) * 68 + 8 * nt + 2 * t4] = st1;
            oacc[nt][0] *= corr0; oacc[nt][1] *= corr0;
            oacc[nt][2] *= corr1; oacc[nt][3] *= corr1;
        }
        ps0 += __shfl_xor_sync(0xffffffffu, ps0, 1);
        ps0 += __shfl_xor_sync(0xffffffffu, ps0, 2);
        ps1 += __shfl_xor_sync(0xffffffffu, ps1, 1);
        ps1 += __shfl_xor_sync(0xffffffffu, ps1, 2);
        l0 = l0 * corr0 + ps0;
        l1 = l1 * corr1 + ps1;

        __syncwarp();   // P stripe visible within warp

        // O += P V
#pragma unroll
        for (int kk = 0; kk < 8; kk++) {
            uint32_t pa[4];
            pa[0] = QP[(wr + g) * 68 + t4 + 8 * kk];
            pa[1] = QP[(wr + g + 8) * 68 + t4 + 8 * kk];
            pa[2] = QP[(wr + g) * 68 + t4 + 4 + 8 * kk];
            pa[3] = QP[(wr + g + 8) * 68 + t4 + 4 + 8 * kk];
#pragma unroll
            for (int nt = 0; nt < 8; nt++) {
                uint32_t bf[2];
                bf[0] = Vs[(t4 + 8 * kk) * 72 + g + 8 * nt];
                bf[1] = Vs[(t4 + 4 + 8 * kk) * 72 + g + 8 * nt];
                mma_tf32(oacc[nt], pa, bf);
            }
        }
        __syncwarp();   // P reads done before next iteration's stores
    }

    // epilogue: normalize and write g_att[b, t, h*64 + hs]
    const float inv0 = 1.0f / l0, inv1 = 1.0f / l1;
    const int b = bh >> 4;
    const int h = bh & (H_ - 1);
    const int qrow0 = q0 + wr + g;
    const int qrow1 = qrow0 + 8;
    float* dst0 = g_att + ((size_t)b * T_ + qrow0) * C_ + h * HS_;
    float* dst1 = g_att + ((size_t)b * T_ + qrow1) * C_ + h * HS_;
#pragma unroll
    for (int nt = 0; nt < 8; nt++) {
        float2 v0 = {oacc[nt][0] * inv0, oacc[nt][1] * inv0};
        *(float2*)&dst0[8 * nt + 2 * t4] = v0;
        float2 v1 = {oacc[nt][2] * inv1, oacc[nt][3] * inv1};
        *(float2*)&dst1[8 * nt + 2 * t4] = v1;
    }
}

// ---------------------------------------------------------------------------
extern "C" void kernel_launch(void* const* d_in, const int* in_sizes, int n_in,
                              void* d_out, int out_size)
{
    const float* x  = (const float*)d_in[0];
    const float* Wq = (const float*)d_in[1];
    const float* Wk = (const float*)d_in[2];
    const float* Wv = (const float*)d_in[3];
    const float* Wp = (const float*)d_in[4];
    const float* bp = (const float*)d_in[5];
    float* out = (float*)d_out;

    cudaFuncSetAttribute(flash_mma, cudaFuncAttributeMaxDynamicSharedMemorySize,
                         FA_SMEM_U32 * 4);

    // 0) weight transposes into K-major scratch
    transpose_w<<<dim3(C_ / 32, HS_ / 32, 3 * H_), dim3(32, 8)>>>(Wq, Wk, Wv);
    transpose_wp<<<dim3(C_ / 32, C_ / 32), dim3(32, 8)>>>(Wp);
    // 1) QKV projection (tensor, mma.sync tf32): M=4096, N=3072
    qkv_gemm_mma<<<dim3(3072 / 128, BT_ / 128), 256>>>(x);
    // 2) Causal flash attention (tensor, mma.sync tf32)
    flash_mma<<<dim3(T_ / 64, B_ * H_), 128, FA_SMEM_U32 * 4>>>();
    // 3) Output projection + bias (tensor, mma.sync tf32): M=4096, N=1024
    out_gemm_mma<<<dim3(C_ / 128, BT_ / 128), 256>>>(bp, out);
}

// round 7
// speedup vs baseline: 4.7050x; 1.0659x over previous
#include <cuda_runtime.h>
#include <cstdint>

#define H_  16
#define HS_ 64
#define C_  1024
#define T_  2048
#define B_  2
#define BT_ (B_ * T_)   // 4096
#define LOG2E 1.4426950408889634f

// ---------------------------------------------------------------------------
// Scratch (no device allocation allowed)
// ---------------------------------------------------------------------------
__device__ float g_q[B_ * H_ * T_ * HS_];
__device__ float g_k[B_ * H_ * T_ * HS_];
__device__ float g_v[B_ * H_ * T_ * HS_];
__device__ float g_att[BT_ * C_];
__device__ float g_bt[3 * H_ * HS_ * C_];   // K-major QKV weights: [3072][1024]
__device__ float g_wpt[C_ * C_];            // K-major Wp: [n][k]

// ---------------------------------------------------------------------------
__device__ __forceinline__ uint32_t f2tf32(float f) {
    uint32_t r;
    asm("cvt.rna.tf32.f32 %0, %1;" : "=r"(r) : "f"(f));
    return r;
}
__device__ __forceinline__ float ex2f(float x) {
    float y;
    asm("ex2.approx.f32 %0, %1;" : "=f"(y) : "f"(x));
    return y;
}
__device__ __forceinline__ void mma_tf32(float c[4], const uint32_t a[4],
                                         const uint32_t b[2]) {
    asm volatile(
        "mma.sync.aligned.m16n8k8.row.col.f32.tf32.tf32.f32 "
        "{%0,%1,%2,%3}, {%4,%5,%6,%7}, {%8,%9}, {%0,%1,%2,%3};"
        : "+f"(c[0]), "+f"(c[1]), "+f"(c[2]), "+f"(c[3])
        : "r"(a[0]), "r"(a[1]), "r"(a[2]), "r"(a[3]), "r"(b[0]), "r"(b[1]));
}

// ---------------------------------------------------------------------------
// Weight transposes into K-major scratch
// ---------------------------------------------------------------------------
__global__ void transpose_w(const float* __restrict__ Wq,
                            const float* __restrict__ Wk,
                            const float* __restrict__ Wv)
{
    __shared__ float tile[32][33];
    const int which = blockIdx.z >> 4;         // 0..2
    const int h     = blockIdx.z & 15;
    const float* W  = (which == 0) ? Wq : (which == 1) ? Wk : Wv;
    const int c0 = blockIdx.x * 32;
    const int d0 = blockIdx.y * 32;
    const int tx = threadIdx.x, ty = threadIdx.y;
#pragma unroll
    for (int j = 0; j < 32; j += 8)
        tile[ty + j][tx] = W[h * (C_ * HS_) + (c0 + ty + j) * HS_ + d0 + tx];
    __syncthreads();
    float* out = g_bt + (size_t)(which * 1024 + h * HS_ + d0) * C_ + c0;
#pragma unroll
    for (int j = 0; j < 32; j += 8)
        out[(ty + j) * C_ + tx] = tile[tx][ty + j];
}

__global__ void transpose_wp(const float* __restrict__ Wp)
{
    __shared__ float tile[32][33];
    const int k0 = blockIdx.x * 32;
    const int n0 = blockIdx.y * 32;
    const int tx = threadIdx.x, ty = threadIdx.y;
#pragma unroll
    for (int j = 0; j < 32; j += 8)
        tile[ty + j][tx] = Wp[(k0 + ty + j) * C_ + n0 + tx];
    __syncthreads();
#pragma unroll
    for (int j = 0; j < 32; j += 8)
        g_wpt[(size_t)(n0 + ty + j) * C_ + k0 + tx] = tile[tx][ty + j];
}

// ---------------------------------------------------------------------------
// tf32 mma.sync GEMM mainloop: 128x128 block tile, K in 32-chunks.
// Register-prefetch pipelining: next chunk's LDGs issued right after the
// staging barrier, overlapping the current chunk's MMAs.
// ---------------------------------------------------------------------------
__device__ __forceinline__ void gemm_core(
    const float* __restrict__ A, const float* __restrict__ Bt,
    int m0, int n0, float acc[4][4][4],
    uint32_t (*As)[36], uint32_t (*Bs)[36])
{
    const int tid  = threadIdx.x;
    const int wid  = tid >> 5;
    const int lane = tid & 31;
    const int wm = (wid & 1) * 64;
    const int wn = (wid >> 1) * 32;
    const int g  = lane >> 2;
    const int t4 = lane & 3;

    const int lrow = tid >> 3;        // 0..31, + p*32
    const int lc4  = (tid & 7) * 4;   // k-col (floats)

    const float* Ap = A + (size_t)(m0 + lrow) * C_ + lc4;
    const float* Bp = Bt + (size_t)(n0 + lrow) * C_ + lc4;

#pragma unroll
    for (int mt = 0; mt < 4; mt++)
#pragma unroll
        for (int nt = 0; nt < 4; nt++)
#pragma unroll
            for (int i = 0; i < 4; i++) acc[mt][nt][i] = 0.f;

    float4 ra[4], rb[4];
#pragma unroll
    for (int p = 0; p < 4; p++) {
        ra[p] = *(const float4*)(Ap + (size_t)p * 32 * C_);
        rb[p] = *(const float4*)(Bp + (size_t)p * 32 * C_);
    }

#pragma unroll 1
    for (int it = 0; it < 32; ++it) {
#pragma unroll
        for (int p = 0; p < 4; p++) {
            uint4 ta = {f2tf32(ra[p].x), f2tf32(ra[p].y),
                        f2tf32(ra[p].z), f2tf32(ra[p].w)};
            *(uint4*)&As[lrow + p * 32][lc4] = ta;
            uint4 tb = {f2tf32(rb[p].x), f2tf32(rb[p].y),
                        f2tf32(rb[p].z), f2tf32(rb[p].w)};
            *(uint4*)&Bs[lrow + p * 32][lc4] = tb;
        }
        __syncthreads();

        if (it < 31) {   // prefetch next chunk; LDGs overlap the MMAs below
            const int kn = (it + 1) * 32;
#pragma unroll
            for (int p = 0; p < 4; p++) {
                ra[p] = *(const float4*)(Ap + kn + (size_t)p * 32 * C_);
                rb[p] = *(const float4*)(Bp + kn + (size_t)p * 32 * C_);
            }
        }

#pragma unroll
        for (int ks = 0; ks < 4; ks++) {
            const int k = ks * 8;
            uint32_t af[4][4], bf[4][2];
#pragma unroll
            for (int mt = 0; mt < 4; mt++) {
                const int r = wm + mt * 16 + g;
                af[mt][0] = As[r][k + t4];
                af[mt][1] = As[r + 8][k + t4];
                af[mt][2] = As[r][k + t4 + 4];
                af[mt][3] = As[r + 8][k + t4 + 4];
            }
#pragma unroll
            for (int nt = 0; nt < 4; nt++) {
                const int n = wn + nt * 8 + g;
                bf[nt][0] = Bs[n][k + t4];
                bf[nt][1] = Bs[n][k + t4 + 4];
            }
#pragma unroll
            for (int mt = 0; mt < 4; mt++)
#pragma unroll
                for (int nt = 0; nt < 4; nt++)
                    mma_tf32(acc[mt][nt], af[mt], bf[nt]);
        }
        __syncthreads();
    }
}

// ---------------------------------------------------------------------------
// QKV projection: M=4096 (b,t), N=3072 (qkv,h,d), K=1024
// ---------------------------------------------------------------------------
__global__ __launch_bounds__(256) void qkv_gemm_mma(const float* __restrict__ x)
{
    __shared__ uint32_t As[128][36];
    __shared__ uint32_t Bs[128][36];
    const int m0 = blockIdx.y * 128;
    const int n0 = blockIdx.x * 128;

    float acc[4][4][4];
    gemm_core(x, g_bt, m0, n0, acc, As, Bs);

    const int tid  = threadIdx.x;
    const int wid  = tid >> 5;
    const int lane = tid & 31;
    const int wm = (wid & 1) * 64;
    const int wn = (wid >> 1) * 32;
    const int g  = lane >> 2;
    const int t4 = lane & 3;

#pragma unroll
    for (int mt = 0; mt < 4; mt++) {
#pragma unroll
        for (int nt = 0; nt < 4; nt++) {
            const int n  = n0 + wn + nt * 8 + t4 * 2;
            const int qk = n >> 10;
            const int h2 = (n >> 6) & (H_ - 1);
            const int d2 = n & (HS_ - 1);
            float* base = ((qk == 0) ? g_q : (qk == 1) ? g_k : g_v);
#pragma unroll
            for (int half = 0; half < 2; half++) {
                const int m = m0 + wm + mt * 16 + g + half * 8;
                const int b = m >> 11;
                const int t = m & (T_ - 1);
                float2 v;
                v.x = acc[mt][nt][half * 2 + 0];
                v.y = acc[mt][nt][half * 2 + 1];
                *(float2*)&base[(((size_t)b * H_ + h2) * T_ + t) * HS_ + d2] = v;
            }
        }
    }
}

// ---------------------------------------------------------------------------
// Output projection: M=4096, N=1024, K=1024, + bias
// ---------------------------------------------------------------------------
__global__ __launch_bounds__(256) void out_gemm_mma(const float* __restrict__ bp,
                                                    float* __restrict__ out)
{
    __shared__ uint32_t As[128][36];
    __shared__ uint32_t Bs[128][36];
    const int m0 = blockIdx.y * 128;
    const int n0 = blockIdx.x * 128;

    float acc[4][4][4];
    gemm_core(g_att, g_wpt, m0, n0, acc, As, Bs);

    const int tid  = threadIdx.x;
    const int wid  = tid >> 5;
    const int lane = tid & 31;
    const int wm = (wid & 1) * 64;
    const int wn = (wid >> 1) * 32;
    const int g  = lane >> 2;
    const int t4 = lane & 3;

#pragma unroll
    for (int mt = 0; mt < 4; mt++) {
#pragma unroll
        for (int nt = 0; nt < 4; nt++) {
            const int n = n0 + wn + nt * 8 + t4 * 2;
            const float2 bias = *(const float2*)(bp + n);
#pragma unroll
            for (int half = 0; half < 2; half++) {
                const int m = m0 + wm + mt * 16 + g + half * 8;
                float2 v;
                v.x = acc[mt][nt][half * 2 + 0] + bias.x;
                v.y = acc[mt][nt][half * 2 + 1] + bias.y;
                *(float2*)&out[(size_t)m * C_ + n] = v;
            }
        }
    }
}

// ---------------------------------------------------------------------------
// Flash attention with tf32 mma.sync. One block = 64 q rows of one (b,h).
// 4 warps; warp w owns the 16-row stripe [w*16, w*16+16).
// P stays in registers: the C-fragment of S is permuted into the
// A-fragment layout for P·V via intra-warp shuffles (no SMEM round trip).
// SMEM (tf32 u32): Ks[64][68] (also used to stage Q), Vs[64][72].
// ---------------------------------------------------------------------------
#define FA_SMEM_U32 (64 * 68 + 64 * 72)

__global__ __launch_bounds__(128, 3) void flash_mma()
{
    extern __shared__ uint32_t sm[];
    uint32_t* Ks = sm;                    // [64][68]
    uint32_t* Vs = sm + 64 * 68;          // [64][72]

    const int qt  = gridDim.x - 1 - blockIdx.x;   // long blocks first
    const int bh  = blockIdx.y;
    const int tid = threadIdx.x;
    const int wid = tid >> 5, lane = tid & 31;
    const int g = lane >> 2, t4 = lane & 3;
    const int wr = wid * 16;
    const int q0 = qt * 64;

    const float* qb = g_q + (size_t)bh * T_ * HS_;
    const float* kb = g_k + (size_t)bh * T_ * HS_;
    const float* vb = g_v + (size_t)bh * T_ * HS_;

    // stage Q through Ks (scale folded: 1/sqrt(HS) * log2(e)), tf32
    const float qscale = 0.125f * LOG2E;
#pragma unroll
    for (int it = 0; it < 8; it++) {
        int l = it * 128 + tid, r = l >> 4, c4 = (l & 15) * 4;
        float4 v = *(const float4*)(qb + (size_t)(q0 + r) * HS_ + c4);
        uint32_t* d = &Ks[r * 68 + c4];
        d[0] = f2tf32(v.x * qscale); d[1] = f2tf32(v.y * qscale);
        d[2] = f2tf32(v.z * qscale); d[3] = f2tf32(v.w * qscale);
    }
    __syncthreads();

    uint32_t qa[8][4];
#pragma unroll
    for (int kk = 0; kk < 8; kk++) {
        qa[kk][0] = Ks[(wr + g) * 68 + t4 + 8 * kk];
        qa[kk][1] = Ks[(wr + g + 8) * 68 + t4 + 8 * kk];
        qa[kk][2] = Ks[(wr + g) * 68 + t4 + 4 + 8 * kk];
        qa[kk][3] = Ks[(wr + g + 8) * 68 + t4 + 4 + 8 * kk];
    }

    float oacc[8][4];
#pragma unroll
    for (int nt = 0; nt < 8; nt++)
#pragma unroll
        for (int i = 0; i < 4; i++) oacc[nt][i] = 0.f;
    float m0 = -1e30f, m1 = -1e30f, l0 = 0.f, l1 = 0.f;

    // P shuffle mapping: P[g][t4+8kk] lives in lane g*4+(t4>>1), comp t4&1
    const int src0 = g * 4 + (t4 >> 1);
    const int src2 = src0 + 2;
    const bool sel = (t4 & 1) != 0;

#pragma unroll 1
    for (int kt = 0; kt <= qt; kt++) {
        const int k0 = kt * 64;
        __syncthreads();   // prior tile's Ks/Vs consumers (and qa reads) done
#pragma unroll
        for (int it = 0; it < 8; it++) {
            int l = it * 128 + tid, r = l >> 4, c4 = (l & 15) * 4;
            float4 kv = *(const float4*)(kb + (size_t)(k0 + r) * HS_ + c4);
            uint32_t* dk = &Ks[r * 68 + c4];
            dk[0] = f2tf32(kv.x); dk[1] = f2tf32(kv.y);
            dk[2] = f2tf32(kv.z); dk[3] = f2tf32(kv.w);
            float4 vv = *(const float4*)(vb + (size_t)(k0 + r) * HS_ + c4);
            uint32_t* dv = &Vs[r * 72 + c4];
            dv[0] = f2tf32(vv.x); dv[1] = f2tf32(vv.y);
            dv[2] = f2tf32(vv.z); dv[3] = f2tf32(vv.w);
        }
        __syncthreads();

        // S = Q K^T  (units: log2)
        float sacc[8][4];
#pragma unroll
        for (int nt = 0; nt < 8; nt++)
#pragma unroll
            for (int i = 0; i < 4; i++) sacc[nt][i] = 0.f;
#pragma unroll
        for (int kk = 0; kk < 8; kk++) {
#pragma unroll
            for (int nt = 0; nt < 8; nt++) {
                uint32_t bf[2];
                bf[0] = Ks[(g + 8 * nt) * 68 + t4 + 8 * kk];
                bf[1] = Ks[(g + 8 * nt) * 68 + t4 + 4 + 8 * kk];
                mma_tf32(sacc[nt], qa[kk], bf);
            }
        }

        if (kt == qt) {   // causal mask on the diagonal tile (local coords)
            const int r0 = wr + g, r1 = wr + g + 8;
#pragma unroll
            for (int nt = 0; nt < 8; nt++) {
                const int c = 8 * nt + 2 * t4;
                if (c     > r0) sacc[nt][0] = -1e30f;
                if (c + 1 > r0) sacc[nt][1] = -1e30f;
                if (c     > r1) sacc[nt][2] = -1e30f;
                if (c + 1 > r1) sacc[nt][3] = -1e30f;
            }
        }

        // online softmax (base 2)
        float ml0 = -1e30f, ml1 = -1e30f;
#pragma unroll
        for (int nt = 0; nt < 8; nt++) {
            ml0 = fmaxf(ml0, fmaxf(sacc[nt][0], sacc[nt][1]));
            ml1 = fmaxf(ml1, fmaxf(sacc[nt][2], sacc[nt][3]));
        }
        ml0 = fmaxf(ml0, __shfl_xor_sync(0xffffffffu, ml0, 1));
        ml0 = fmaxf(ml0, __shfl_xor_sync(0xffffffffu, ml0, 2));
        ml1 = fmaxf(ml1, __shfl_xor_sync(0xffffffffu, ml1, 1));
        ml1 = fmaxf(ml1, __shfl_xor_sync(0xffffffffu, ml1, 2));
        const float mn0 = fmaxf(m0, ml0), mn1 = fmaxf(m1, ml1);
        const float corr0 = ex2f(m0 - mn0), corr1 = ex2f(m1 - mn1);
        m0 = mn0; m1 = mn1;

        uint32_t pu[8][4];
        float ps0 = 0.f, ps1 = 0.f;
#pragma unroll
        for (int nt = 0; nt < 8; nt++) {
            float p00 = ex2f(sacc[nt][0] - mn0);
            float p01 = ex2f(sacc[nt][1] - mn0);
            float p10 = ex2f(sacc[nt][2] - mn1);
            float p11 = ex2f(sacc[nt][3] - mn1);
            ps0 += p00 + p01;
            ps1 += p10 + p11;
            pu[nt][0] = f2tf32(p00); pu[nt][1] = f2tf32(p01);
            pu[nt][2] = f2tf32(p10); pu[nt][3] = f2tf32(p11);
            oacc[nt][0] *= corr0; oacc[nt][1] *= corr0;
            oacc[nt][2] *= corr1; oacc[nt][3] *= corr1;
        }
        ps0 += __shfl_xor_sync(0xffffffffu, ps0, 1);
        ps0 += __shfl_xor_sync(0xffffffffu, ps0, 2);
        ps1 += __shfl_xor_sync(0xffffffffu, ps1, 1);
        ps1 += __shfl_xor_sync(0xffffffffu, ps1, 2);
        l0 = l0 * corr0 + ps0;
        l1 = l1 * corr1 + ps1;

        // O += P V  (P redistributed C-frag -> A-frag via shuffles)
#pragma unroll
        for (int kk = 0; kk < 8; kk++) {
            uint32_t pa[4];
            uint32_t v0 = __shfl_sync(0xffffffffu, pu[kk][0], src0);
            uint32_t v1 = __shfl_sync(0xffffffffu, pu[kk][1], src0);
            uint32_t v2 = __shfl_sync(0xffffffffu, pu[kk][2], src0);
            uint32_t v3 = __shfl_sync(0xffffffffu, pu[kk][3], src0);
            pa[0] = sel ? v1 : v0;    // P[g][t4+8kk]
            pa[1] = sel ? v3 : v2;    // P[g+8][t4+8kk]
            uint32_t w0 = __shfl_sync(0xffffffffu, pu[kk][0], src2);
            uint32_t w1 = __shfl_sync(0xffffffffu, pu[kk][1], src2);
            uint32_t w2 = __shfl_sync(0xffffffffu, pu[kk][2], src2);
            uint32_t w3 = __shfl_sync(0xffffffffu, pu[kk][3], src2);
            pa[2] = sel ? w1 : w0;    // P[g][t4+4+8kk]
            pa[3] = sel ? w3 : w2;    // P[g+8][t4+4+8kk]
#pragma unroll
            for (int nt = 0; nt < 8; nt++) {
                uint32_t bf[2];
                bf[0] = Vs[(t4 + 8 * kk) * 72 + g + 8 * nt];
                bf[1] = Vs[(t4 + 4 + 8 * kk) * 72 + g + 8 * nt];
                mma_tf32(oacc[nt], pa, bf);
            }
        }
    }

    // epilogue: normalize and write g_att[b, t, h*64 + hs]
    const float inv0 = 1.0f / l0, inv1 = 1.0f / l1;
    const int b = bh >> 4;
    const int h = bh & (H_ - 1);
    const int qrow0 = q0 + wr + g;
    const int qrow1 = qrow0 + 8;
    float* dst0 = g_att + ((size_t)b * T_ + qrow0) * C_ + h * HS_;
    float* dst1 = g_att + ((size_t)b * T_ + qrow1) * C_ + h * HS_;
#pragma unroll
    for (int nt = 0; nt < 8; nt++) {
        float2 v0 = {oacc[nt][0] * inv0, oacc[nt][1] * inv0};
        *(float2*)&dst0[8 * nt + 2 * t4] = v0;
        float2 v1 = {oacc[nt][2] * inv1, oacc[nt][3] * inv1};
        *(float2*)&dst1[8 * nt + 2 * t4] = v1;
    }
}

// ---------------------------------------------------------------------------
extern "C" void kernel_launch(void* const* d_in, const int* in_sizes, int n_in,
                              void* d_out, int out_size)
{
    const float* x  = (const float*)d_in[0];
    const float* Wq = (const float*)d_in[1];
    const float* Wk = (const float*)d_in[2];
    const float* Wv = (const float*)d_in[3];
    const float* Wp = (const float*)d_in[4];
    const float* bp = (const float*)d_in[5];
    float* out = (float*)d_out;

    cudaFuncSetAttribute(flash_mma, cudaFuncAttributeMaxDynamicSharedMemorySize,
                         FA_SMEM_U32 * 4);

    // 0) weight transposes into K-major scratch
    transpose_w<<<dim3(C_ / 32, HS_ / 32, 3 * H_), dim3(32, 8)>>>(Wq, Wk, Wv);
    transpose_wp<<<dim3(C_ / 32, C_ / 32), dim3(32, 8)>>>(Wp);
    // 1) QKV projection (tensor, mma.sync tf32): M=4096, N=3072
    qkv_gemm_mma<<<dim3(3072 / 128, BT_ / 128), 256>>>(x);
    // 2) Causal flash attention (tensor, mma.sync tf32, register P)
    flash_mma<<<dim3(T_ / 64, B_ * H_), 128, FA_SMEM_U32 * 4>>>();
    // 3) Output projection + bias (tensor, mma.sync tf32): M=4096, N=1024
    out_gemm_mma<<<dim3(C_ / 128, BT_ / 128), 256>>>(bp, out);
}